// round 3
// baseline (speedup 1.0000x reference)
#include <cuda_runtime.h>

// u: [16384, 2, 2048] float32 -> out: [16384, 2, 2048] float32
// du = 6th-order central diff along l (interior [10, 2038)), zero in ghosts.
// out[:,0,:] = -(u1*du0 + u0*du1)
// out[:,1,:] = -(2*du0 + u1*du1)
// Ghost outputs are exactly zero (du==0 makes both combine terms vanish).

#define L 2048
#define IGST 10
#define ROW 4096   // 2 channels * L

__global__ __launch_bounds__(256) void centdif_kernel(const float* __restrict__ u,
                                                      float* __restrict__ out) {
    const int t = threadIdx.x;
    const long base = (long)blockIdx.x * ROW;
    const float4* __restrict__ up = (const float4*)(u + base);
    float4* __restrict__ op = (float4*)(out + base);

    // Each thread owns 8 outputs per channel: l = 8t .. 8t+7.
    // Threads 0 and 255 cover only ghost cells -> write zeros, no loads
    // (also guarantees the window loads below stay in-bounds).
    if (t == 0 || t == 255) {
        const float4 z = make_float4(0.f, 0.f, 0.f, 0.f);
        op[2 * t] = z;
        op[2 * t + 1] = z;
        op[512 + 2 * t] = z;
        op[512 + 2 * t + 1] = z;
        return;
    }

    // Window: floats l0-4 .. l0+11 per channel = 4 aligned float4 starting at chunk 2t-1.
    const int c0 = 2 * t - 1;
    float w0[16], w1[16];
#pragma unroll
    for (int j = 0; j < 4; j++) {
        const float4 a = up[c0 + j];
        w0[4 * j + 0] = a.x; w0[4 * j + 1] = a.y; w0[4 * j + 2] = a.z; w0[4 * j + 3] = a.w;
    }
#pragma unroll
    for (int j = 0; j < 4; j++) {
        const float4 b = up[512 + c0 + j];
        w1[4 * j + 0] = b.x; w1[4 * j + 1] = b.y; w1[4 * j + 2] = b.z; w1[4 * j + 3] = b.w;
    }

    const float c = 1.0f / (60.0f * 0.012f);
    const int l0 = 8 * t;
    float o0[8], o1[8];
#pragma unroll
    for (int k = 0; k < 8; k++) {
        const int p = l0 + k;
        const bool in = (p >= IGST) && (p < L - IGST);
        float du0 = (-w0[k + 1] + 9.0f * w0[k + 2] - 45.0f * w0[k + 3]
                     + 45.0f * w0[k + 5] - 9.0f * w0[k + 6] + w0[k + 7]) * c;
        float du1 = (-w1[k + 1] + 9.0f * w1[k + 2] - 45.0f * w1[k + 3]
                     + 45.0f * w1[k + 5] - 9.0f * w1[k + 6] + w1[k + 7]) * c;
        du0 = in ? du0 : 0.0f;
        du1 = in ? du1 : 0.0f;
        const float u0 = w0[k + 4];
        const float u1 = w1[k + 4];
        o0[k] = -(u1 * du0 + u0 * du1);
        o1[k] = -(2.0f * du0 + u1 * du1);
    }

    op[2 * t]           = make_float4(o0[0], o0[1], o0[2], o0[3]);
    op[2 * t + 1]       = make_float4(o0[4], o0[5], o0[6], o0[7]);
    op[512 + 2 * t]     = make_float4(o1[0], o1[1], o1[2], o1[3]);
    op[512 + 2 * t + 1] = make_float4(o1[4], o1[5], o1[6], o1[7]);
}

extern "C" void kernel_launch(void* const* d_in, const int* in_sizes, int n_in,
                              void* d_out, int out_size) {
    const float* u = (const float*)d_in[0];
    float* out = (float*)d_out;
    const int m = in_sizes[0] / ROW;  // 16384
    centdif_kernel<<<m, 256>>>(u, out);
}